// round 2
// baseline (speedup 1.0000x reference)
#include <cuda_runtime.h>
#include <cuda_bf16.h>
#include <cstddef>

#define TPB      512
#define NFFT     4096
#define CST      4356                 // per-column smem stride (float2), 4096 + pad + bank skew
#define PHYS(i)  ((i) + ((i) >> 4))   // data padding: every 16 elements
#define PHYT(i)  ((i) + ((i) >> 4) + ((i) >> 6))  // twiddle-table padding
#define TWSZ     4416                 // PHYT(4095)+1 = 4413, rounded up

__device__ __forceinline__ float2 cmul(float2 a, float2 b) {
    return make_float2(fmaf(a.x, b.x, -a.y * b.y), fmaf(a.x, b.y, a.y * b.x));
}
// a * conj(b)
__device__ __forceinline__ float2 cmulc(float2 a, float2 b) {
    return make_float2(fmaf(a.x, b.x, a.y * b.y), fmaf(a.y, b.x, -a.x * b.y));
}

__device__ __forceinline__ void dft4(float2 &a, float2 &b, float2 &c, float2 &d) {
    float2 t0 = make_float2(a.x + c.x, a.y + c.y);
    float2 t1 = make_float2(a.x - c.x, a.y - c.y);
    float2 t2 = make_float2(b.x + d.x, b.y + d.y);
    float2 t3 = make_float2(b.x - d.x, b.y - d.y);
    a = make_float2(t0.x + t2.x, t0.y + t2.y);
    c = make_float2(t0.x - t2.x, t0.y - t2.y);
    b = make_float2(t1.x + t3.y, t1.y - t3.x);   // t1 - i*t3
    d = make_float2(t1.x - t3.y, t1.y + t3.x);   // t1 + i*t3
}

// 16-point forward DFT, natural input order j. Output X[m] ends at slot
// ((m&3)<<2)|(m>>2).
__device__ __forceinline__ void dft16(float2 v[16]) {
    #pragma unroll
    for (int j0 = 0; j0 < 4; j0++) dft4(v[j0], v[j0 + 4], v[j0 + 8], v[j0 + 12]);
    const float C1 = 0.92387953251128675613f;   // cos(pi/8)
    const float S1 = 0.38268343236508977173f;   // sin(pi/8)
    const float C2 = 0.70710678118654752440f;   // sqrt(2)/2
    v[5]  = cmul(v[5],  make_float2( C1, -S1));   // w16^1
    v[9]  = cmul(v[9],  make_float2( C2, -C2));   // w16^2
    v[13] = cmul(v[13], make_float2( S1, -C1));   // w16^3
    v[6]  = cmul(v[6],  make_float2( C2, -C2));   // w16^2
    { float2 t = v[10]; v[10] = make_float2(t.y, -t.x); }   // w16^4 = -i
    v[14] = cmul(v[14], make_float2(-C2, -C2));   // w16^6
    v[7]  = cmul(v[7],  make_float2( S1, -C1));   // w16^3
    v[11] = cmul(v[11], make_float2(-C2, -C2));   // w16^6
    v[15] = cmul(v[15], make_float2(-C1,  S1));   // w16^9
    #pragma unroll
    for (int m0 = 0; m0 < 4; m0++) dft4(v[4*m0], v[4*m0+1], v[4*m0+2], v[4*m0+3]);
}

// Forward radix-4 DIF pass, sub-transform size L = 4*Q, Q = 1<<LOG2Q.
template <int LOG2Q>
__device__ __forceinline__ void dif_pass(float2 *sm, const float2 *tw, int tid) {
    const int Q = 1 << LOG2Q;
    for (int it = 0; it < 8; it++) {
        int idx = it * TPB + tid;
        float2 *Bp = sm + (idx >> 10) * CST;
        int wi = idx & 1023;
        int j  = wi & (Q - 1);
        int g  = wi >> LOG2Q;
        int i0 = g * (Q * 4) + j;
        float2 a = Bp[PHYS(i0)];
        float2 b = Bp[PHYS(i0 + Q)];
        float2 c = Bp[PHYS(i0 + 2*Q)];
        float2 d = Bp[PHYS(i0 + 3*Q)];
        float2 t0 = make_float2(a.x + c.x, a.y + c.y);
        float2 t1 = make_float2(a.x - c.x, a.y - c.y);
        float2 t2 = make_float2(b.x + d.x, b.y + d.y);
        float2 t3 = make_float2(b.x - d.x, b.y - d.y);
        float2 A0 = make_float2(t0.x + t2.x, t0.y + t2.y);
        float2 A1 = make_float2(t1.x + t3.y, t1.y - t3.x);   // t1 - i*t3
        float2 A2 = make_float2(t0.x - t2.x, t0.y - t2.y);
        float2 A3 = make_float2(t1.x - t3.y, t1.y + t3.x);   // t1 + i*t3
        int e = j << (10 - LOG2Q);
        Bp[PHYS(i0)]       = A0;
        Bp[PHYS(i0 + Q)]   = cmul(A1, tw[PHYT(e)]);
        Bp[PHYS(i0 + 2*Q)] = cmul(A2, tw[PHYT(2*e)]);
        Bp[PHYS(i0 + 3*Q)] = cmul(A3, tw[PHYT(3*e)]);
    }
    __syncthreads();
}

// Inverse radix-4 DIT pass (conjugate twiddles), sub-transform size L = 4*Q.
template <int LOG2Q>
__device__ __forceinline__ void dit_pass(float2 *sm, const float2 *tw, int tid) {
    const int Q = 1 << LOG2Q;
    for (int it = 0; it < 8; it++) {
        int idx = it * TPB + tid;
        float2 *Bp = sm + (idx >> 10) * CST;
        int wi = idx & 1023;
        int j  = wi & (Q - 1);
        int g  = wi >> LOG2Q;
        int i0 = g * (Q * 4) + j;
        int e = j << (10 - LOG2Q);
        float2 a = Bp[PHYS(i0)];
        float2 b = cmulc(Bp[PHYS(i0 + Q)],   tw[PHYT(e)]);
        float2 c = cmulc(Bp[PHYS(i0 + 2*Q)], tw[PHYT(2*e)]);
        float2 d = cmulc(Bp[PHYS(i0 + 3*Q)], tw[PHYT(3*e)]);
        float2 t0 = make_float2(a.x + c.x, a.y + c.y);
        float2 t1 = make_float2(a.x - c.x, a.y - c.y);
        float2 t2 = make_float2(b.x + d.x, b.y + d.y);
        float2 t3 = make_float2(b.x - d.x, b.y - d.y);
        Bp[PHYS(i0)]       = make_float2(t0.x + t2.x, t0.y + t2.y);
        Bp[PHYS(i0 + Q)]   = make_float2(t1.x - t3.y, t1.y + t3.x);   // t1 + i*t3
        Bp[PHYS(i0 + 2*Q)] = make_float2(t0.x - t2.x, t0.y - t2.y);
        Bp[PHYS(i0 + 3*Q)] = make_float2(t1.x + t3.y, t1.y - t3.x);   // t1 - i*t3
    }
    __syncthreads();
}

// Digit reversal for radices [4,4,4,4,16] DIF order (12-bit index).
__device__ __forceinline__ int rev12(int k) {
    return ((k & 3) << 10) | (((k >> 2) & 3) << 8) | (((k >> 4) & 3) << 6) |
           (((k >> 6) & 3) << 4) | (k >> 8);
}

// Unpack -> filter -> repack for one (k, 4096-k) pair, in digit-reversed smem.
__device__ __forceinline__ void filter_pair(float2 *Bp, const float2 *__restrict__ Hb, int k) {
    int km = 4096 - k;
    int pk = PHYS(rev12(k));
    int pm = PHYS(rev12(km));
    float2 Zk = Bp[pk];
    float2 Zm = Bp[pm];
    // Xe = (Zk + conj(Zm))/2 ; Xo = -i*(Zk - conj(Zm))/2
    float2 Xe = make_float2(0.5f * (Zk.x + Zm.x), 0.5f * (Zk.y - Zm.y));
    float2 u  = make_float2(Zk.x - Zm.x, Zk.y + Zm.y);
    float2 Xo = make_float2(0.5f * u.y, -0.5f * u.x);
    float s, co;
    sincospif((float)k * (1.0f / 4096.0f), &s, &co);
    float2 W = make_float2(co, -s);               // e^{-2*pi*i*k/8192}
    float2 WXo = cmul(W, Xo);
    float2 Xk = make_float2(Xe.x + WXo.x, Xe.y + WXo.y);
    float2 Xm = make_float2(Xe.x - WXo.x, -(Xe.y - WXo.y));   // conj(Xe - W*Xo)
    float2 Hk = __ldg(Hb + k);
    float2 Hm = __ldg(Hb + km);
    float2 Yk = cmul(Xk, Hk);
    float2 Ym = cmul(Xm, Hm);
    // Ye = (Yk + conj(Ym))/2 ; Yo = conj(W)*(Yk - conj(Ym))/2
    float2 Ye = make_float2(0.5f * (Yk.x + Ym.x), 0.5f * (Yk.y - Ym.y));
    float2 u2 = make_float2(Yk.x - Ym.x, Yk.y + Ym.y);
    float2 Yo = cmulc(make_float2(0.5f * u2.x, 0.5f * u2.y), W);
    // Zy[k] = Ye + i*Yo ; Zy[4096-k] = conj(Ye - i*Yo)
    Bp[pk] = make_float2(Ye.x - Yo.y, Ye.y + Yo.x);
    Bp[pm] = make_float2(Ye.x + Yo.y, Yo.x - Ye.y);
}

__global__ __launch_bounds__(TPB, 1)
void _ScaleFFTFilter_45380624449589_kernel(const float *__restrict__ x,
                                           const float2 *__restrict__ H2,
                                           float *__restrict__ y) {
    extern __shared__ float2 smem_raw[];
    float2 *sm = smem_raw;             // 4 columns * CST
    float2 *tw = smem_raw + 4 * CST;   // padded twiddle table (TWSZ)

    const int tid = threadIdx.x;
    const int fg  = blockIdx.x >> 3;   // feature group (0..127)
    const int b   = blockIdx.x & 7;    // batch (0..7)
    const int f0  = fg * 4;

    // twiddle table: tw[m] = e^{-2*pi*i*m/4096}
    for (int m = tid; m < NFFT; m += TPB) {
        float s, co;
        sincospif((float)m * (1.0f / 2048.0f), &s, &co);
        tw[PHYT(m)] = make_float2(co, -s);
    }

    // Load + pack: z_c[n] = x[b, 2n, f0+c] + i*x[b, 2n+1, f0+c]
    const float *xb = x + ((size_t)b * 8192) * 512 + f0;
    {
        // overlap table init with first loads? keep simple: sync after both
        for (int it = 0; it < 32; it++) {
            int idx = it * TPB + tid;
            int cc = idx & 3;
            int n  = idx >> 2;
            float xr = __ldg(xb + (size_t)(2 * n) * 512 + cc);
            float xi = __ldg(xb + (size_t)(2 * n + 1) * 512 + cc);
            sm[cc * CST + PHYS(n)] = make_float2(xr, xi);
        }
    }
    __syncthreads();

    // ---- forward FFT (DIF): output digit-reversed ----
    dif_pass<10>(sm, tw, tid);
    dif_pass<8>(sm, tw, tid);
    dif_pass<6>(sm, tw, tid);
    dif_pass<4>(sm, tw, tid);
    // final radix-16 blocks (no twiddles)
    for (int it = 0; it < 2; it++) {
        int idx = it * TPB + tid;
        float2 *Bp = sm + (idx >> 8) * CST;
        int base = (idx & 255) * 16;
        float2 v[16];
        #pragma unroll
        for (int j = 0; j < 16; j++) v[j] = Bp[PHYS(base + j)];
        dft16(v);
        #pragma unroll
        for (int m = 0; m < 16; m++) Bp[PHYS(base + m)] = v[((m & 3) << 2) | (m >> 2)];
    }
    __syncthreads();

    // ---- unpack -> filter -> repack (digit-reversed domain) ----
    for (int it = 0; it < 16; it++) {
        int idx = it * TPB + tid;
        int cc = idx >> 11;
        int q  = idx & 2047;
        float2 *Bp = sm + cc * CST;
        const float2 *Hb = H2 + (size_t)(f0 + cc) * 4097;
        if (q == 0) {
            // bins 0 and 4096 (both real after imag-drop)
            float2 z0 = Bp[PHYS(0)];
            float X0 = z0.x + z0.y;
            float XN = z0.x - z0.y;
            float Y0 = X0 * __ldg(Hb + 0).x;
            float YN = XN * __ldg(Hb + 4096).x;
            Bp[PHYS(0)] = make_float2(0.5f * (Y0 + YN), 0.5f * (Y0 - YN));
        } else {
            int k = ((q & 15) << 7) | (q >> 4);   // bank-friendly enumeration of 1..2047
            filter_pair(Bp, Hb, k);
        }
    }
    if (tid < 4) {   // self-paired bin k = 2048 (one per column; disjoint smem slot)
        filter_pair(sm + tid * CST, H2 + (size_t)(f0 + tid) * 4097, 2048);
    }
    __syncthreads();

    // ---- inverse FFT (DIT): digit-reversed in, natural out ----
    // first: inverse radix-16 blocks (no twiddles)
    for (int it = 0; it < 2; it++) {
        int idx = it * TPB + tid;
        float2 *Bp = sm + (idx >> 8) * CST;
        int base = (idx & 255) * 16;
        float2 v[16];
        #pragma unroll
        for (int j = 0; j < 16; j++) {
            float2 u = Bp[PHYS(base + j)];
            v[j] = make_float2(u.x, -u.y);
        }
        dft16(v);
        #pragma unroll
        for (int q = 0; q < 16; q++) {
            float2 w = v[((q & 3) << 2) | (q >> 2)];
            Bp[PHYS(base + q)] = make_float2(w.x, -w.y);
        }
    }
    __syncthreads();
    dit_pass<4>(sm, tw, tid);
    dit_pass<6>(sm, tw, tid);
    dit_pass<8>(sm, tw, tid);
    dit_pass<10>(sm, tw, tid);

    // ---- unpack to real output (scale 1/4096) ----
    float *yb = y + ((size_t)b * 8192) * 512 + f0;
    const float SC = 1.0f / 4096.0f;
    for (int it = 0; it < 32; it++) {
        int idx = it * TPB + tid;
        int cc = idx & 3;
        int n  = idx >> 2;
        float2 v = sm[cc * CST + PHYS(n)];
        yb[(size_t)(2 * n) * 512 + cc]     = v.x * SC;
        yb[(size_t)(2 * n + 1) * 512 + cc] = v.y * SC;
    }
}

extern "C" void kernel_launch(void* const* d_in, const int* in_sizes, int n_in,
                              void* d_out, int out_size) {
    (void)in_sizes; (void)n_in; (void)out_size;
    const float  *x  = (const float*)d_in[0];
    const float2 *H2 = (const float2*)d_in[1];
    float        *y  = (float*)d_out;

    const size_t smem_bytes = (size_t)(4 * CST + TWSZ) * sizeof(float2);  // ~174.7 KB
    cudaFuncSetAttribute(_ScaleFFTFilter_45380624449589_kernel,
                         cudaFuncAttributeMaxDynamicSharedMemorySize,
                         (int)smem_bytes);
    _ScaleFFTFilter_45380624449589_kernel<<<1024, TPB, smem_bytes>>>(x, H2, y);
}

// round 3
// speedup vs baseline: 1.2397x; 1.2397x over previous
#include <cuda_runtime.h>
#include <cuda_bf16.h>
#include <cstddef>

#define TPB      512
#define NFFT     4096
#define CST      4356                 // per-column smem stride (float2)
#define PHYS(i)  ((i) + ((i) >> 4))   // data padding: every 16 elements
#define PHYT(i)  ((i) + ((i) >> 4) + ((i) >> 6))  // twiddle-table padding
#define TWN      256                  // table entries needed (max exponent 255)
#define TWSZ     288                  // > PHYT(255) = 273
#define PERM16(m) ((((m) & 3) << 2) | ((m) >> 2))

__device__ __forceinline__ float2 cmul(float2 a, float2 b) {
    return make_float2(fmaf(a.x, b.x, -a.y * b.y), fmaf(a.x, b.y, a.y * b.x));
}
// a * conj(b)
__device__ __forceinline__ float2 cmulc(float2 a, float2 b) {
    return make_float2(fmaf(a.x, b.x, a.y * b.y), fmaf(a.y, b.x, -a.x * b.y));
}

__device__ __forceinline__ void dft4(float2 &a, float2 &b, float2 &c, float2 &d) {
    float2 t0 = make_float2(a.x + c.x, a.y + c.y);
    float2 t1 = make_float2(a.x - c.x, a.y - c.y);
    float2 t2 = make_float2(b.x + d.x, b.y + d.y);
    float2 t3 = make_float2(b.x - d.x, b.y - d.y);
    a = make_float2(t0.x + t2.x, t0.y + t2.y);
    c = make_float2(t0.x - t2.x, t0.y - t2.y);
    b = make_float2(t1.x + t3.y, t1.y - t3.x);   // t1 - i*t3
    d = make_float2(t1.x - t3.y, t1.y + t3.x);   // t1 + i*t3
}

// 16-point forward DFT, natural input order. Output X[m] ends at slot PERM16(m).
__device__ __forceinline__ void dft16(float2 v[16]) {
    #pragma unroll
    for (int j0 = 0; j0 < 4; j0++) dft4(v[j0], v[j0 + 4], v[j0 + 8], v[j0 + 12]);
    const float C1 = 0.92387953251128675613f;   // cos(pi/8)
    const float S1 = 0.38268343236508977173f;   // sin(pi/8)
    const float C2 = 0.70710678118654752440f;   // sqrt(2)/2
    v[5]  = cmul(v[5],  make_float2( C1, -S1));
    v[9]  = cmul(v[9],  make_float2( C2, -C2));
    v[13] = cmul(v[13], make_float2( S1, -C1));
    v[6]  = cmul(v[6],  make_float2( C2, -C2));
    { float2 t = v[10]; v[10] = make_float2(t.y, -t.x); }
    v[14] = cmul(v[14], make_float2(-C2, -C2));
    v[7]  = cmul(v[7],  make_float2( S1, -C1));
    v[11] = cmul(v[11], make_float2(-C2, -C2));
    v[15] = cmul(v[15], make_float2(-C1,  S1));
    #pragma unroll
    for (int m0 = 0; m0 < 4; m0++) dft4(v[4*m0], v[4*m0+1], v[4*m0+2], v[4*m0+3]);
}

// Forward radix-16 DIF pass with twiddles, sub-transform length L = 16*Q.
// Twiddle powers built from ONE table load (w^1) via depth-4 cmul tree.
template <int LOG2Q>
__device__ __forceinline__ void fwd_pass16(float2 *sm, const float2 *tw, int tid) {
    const int Q  = 1 << LOG2Q;
    const int QP = Q + (Q >> 4);       // physical stride (Q multiple of 16)
    #pragma unroll
    for (int it = 0; it < 2; it++) {
        int idx = it * TPB + tid;                    // 0..1023
        float2 *Bp = sm + (idx >> 8) * CST;
        int wi = idx & 255;
        int j  = wi & (Q - 1);
        int g  = wi >> LOG2Q;
        int i0 = g * (16 * Q) + j;
        int p0 = PHYS(i0);
        float2 v[16];
        #pragma unroll
        for (int m = 0; m < 16; m++) v[m] = Bp[p0 + m * QP];
        dft16(v);
        int e = j << (8 - LOG2Q);
        float2 w1 = tw[PHYT(e)];
        Bp[p0] = v[0];
        Bp[p0 +  1 * QP] = cmul(v[PERM16(1)], w1);
        float2 w2 = cmul(w1, w1);
        Bp[p0 +  2 * QP] = cmul(v[PERM16(2)], w2);
        float2 w3 = cmul(w2, w1);
        Bp[p0 +  3 * QP] = cmul(v[PERM16(3)], w3);
        float2 w4 = cmul(w2, w2);
        Bp[p0 +  4 * QP] = cmul(v[PERM16(4)], w4);
        float2 w5 = cmul(w4, w1);
        Bp[p0 +  5 * QP] = cmul(v[PERM16(5)], w5);
        float2 w6 = cmul(w4, w2);
        Bp[p0 +  6 * QP] = cmul(v[PERM16(6)], w6);
        float2 w7 = cmul(w4, w3);
        Bp[p0 +  7 * QP] = cmul(v[PERM16(7)], w7);
        float2 w8 = cmul(w4, w4);
        Bp[p0 +  8 * QP] = cmul(v[PERM16(8)], w8);
        Bp[p0 +  9 * QP] = cmul(v[PERM16(9)],  cmul(w8, w1));
        Bp[p0 + 10 * QP] = cmul(v[PERM16(10)], cmul(w8, w2));
        Bp[p0 + 11 * QP] = cmul(v[PERM16(11)], cmul(w8, w3));
        Bp[p0 + 12 * QP] = cmul(v[PERM16(12)], cmul(w8, w4));
        Bp[p0 + 13 * QP] = cmul(v[PERM16(13)], cmul(w8, w5));
        Bp[p0 + 14 * QP] = cmul(v[PERM16(14)], cmul(w8, w6));
        Bp[p0 + 15 * QP] = cmul(v[PERM16(15)], cmul(w8, w7));
    }
    __syncthreads();
}

// Inverse radix-16 DIT pass (conjugate twiddles), mirror of fwd_pass16.
template <int LOG2Q>
__device__ __forceinline__ void inv_pass16(float2 *sm, const float2 *tw, int tid) {
    const int Q  = 1 << LOG2Q;
    const int QP = Q + (Q >> 4);
    #pragma unroll
    for (int it = 0; it < 2; it++) {
        int idx = it * TPB + tid;
        float2 *Bp = sm + (idx >> 8) * CST;
        int wi = idx & 255;
        int j  = wi & (Q - 1);
        int g  = wi >> LOG2Q;
        int i0 = g * (16 * Q) + j;
        int p0 = PHYS(i0);
        float2 v[16];
        #pragma unroll
        for (int m = 0; m < 16; m++) v[m] = Bp[p0 + m * QP];
        int e = j << (8 - LOG2Q);
        float2 w1 = tw[PHYT(e)];
        // want dft16 input slot m = conj(u[m]) with u[m] = raw * conj(w^m)
        // conj(raw * conj(w)) = w * conj(raw) = cmulc(w, raw)
        v[0] = make_float2(v[0].x, -v[0].y);
        v[1] = cmulc(w1, v[1]);
        float2 w2 = cmul(w1, w1);  v[2] = cmulc(w2, v[2]);
        float2 w3 = cmul(w2, w1);  v[3] = cmulc(w3, v[3]);
        float2 w4 = cmul(w2, w2);  v[4] = cmulc(w4, v[4]);
        float2 w5 = cmul(w4, w1);  v[5] = cmulc(w5, v[5]);
        float2 w6 = cmul(w4, w2);  v[6] = cmulc(w6, v[6]);
        float2 w7 = cmul(w4, w3);  v[7] = cmulc(w7, v[7]);
        float2 w8 = cmul(w4, w4);  v[8] = cmulc(w8, v[8]);
        v[9]  = cmulc(cmul(w8, w1), v[9]);
        v[10] = cmulc(cmul(w8, w2), v[10]);
        v[11] = cmulc(cmul(w8, w3), v[11]);
        v[12] = cmulc(cmul(w8, w4), v[12]);
        v[13] = cmulc(cmul(w8, w5), v[13]);
        v[14] = cmulc(cmul(w8, w6), v[14]);
        v[15] = cmulc(cmul(w8, w7), v[15]);
        dft16(v);
        #pragma unroll
        for (int m = 0; m < 16; m++) {
            float2 w = v[PERM16(m)];
            Bp[p0 + m * QP] = make_float2(w.x, -w.y);
        }
    }
    __syncthreads();
}

// Digit reversal for radices [16,16,16] DIF order (12-bit index).
__device__ __forceinline__ int rev16(int k) {
    return ((k & 15) << 8) | (k & 0xF0) | (k >> 8);
}

// Unpack -> filter -> repack for one (k, 4096-k) pair, in digit-reversed smem.
__device__ __forceinline__ void filter_pair(float2 *Bp, const float2 *__restrict__ Hb, int k) {
    int km = 4096 - k;
    int pk = PHYS(rev16(k));
    int pm = PHYS(rev16(km));
    float2 Zk = Bp[pk];
    float2 Zm = Bp[pm];
    // Xe = (Zk + conj(Zm))/2 ; Xo = -i*(Zk - conj(Zm))/2
    float2 Xe = make_float2(0.5f * (Zk.x + Zm.x), 0.5f * (Zk.y - Zm.y));
    float2 u  = make_float2(Zk.x - Zm.x, Zk.y + Zm.y);
    float2 Xo = make_float2(0.5f * u.y, -0.5f * u.x);
    float s, co;
    sincospif((float)k * (1.0f / 4096.0f), &s, &co);
    float2 W = make_float2(co, -s);               // e^{-2*pi*i*k/8192}
    float2 WXo = cmul(W, Xo);
    float2 Xk = make_float2(Xe.x + WXo.x, Xe.y + WXo.y);
    float2 Xm = make_float2(Xe.x - WXo.x, -(Xe.y - WXo.y));   // conj(Xe - W*Xo)
    float2 Hk = __ldg(Hb + k);
    float2 Hm = __ldg(Hb + km);
    float2 Yk = cmul(Xk, Hk);
    float2 Ym = cmul(Xm, Hm);
    // Ye = (Yk + conj(Ym))/2 ; Yo = conj(W)*(Yk - conj(Ym))/2
    float2 Ye = make_float2(0.5f * (Yk.x + Ym.x), 0.5f * (Yk.y - Ym.y));
    float2 u2 = make_float2(Yk.x - Ym.x, Yk.y + Ym.y);
    float2 Yo = cmulc(make_float2(0.5f * u2.x, 0.5f * u2.y), W);
    // Zy[k] = Ye + i*Yo ; Zy[4096-k] = conj(Ye - i*Yo)
    Bp[pk] = make_float2(Ye.x - Yo.y, Ye.y + Yo.x);
    Bp[pm] = make_float2(Ye.x + Yo.y, Yo.x - Ye.y);
}

__global__ __launch_bounds__(TPB, 1)
void _ScaleFFTFilter_45380624449589_kernel(const float *__restrict__ x,
                                           const float2 *__restrict__ H2,
                                           float *__restrict__ y) {
    extern __shared__ float2 smem_raw[];
    float2 *sm = smem_raw;             // 4 columns * CST
    float2 *tw = smem_raw + 4 * CST;   // padded twiddle table (TWSZ)

    const int tid = threadIdx.x;
    const int fg  = blockIdx.x >> 3;   // feature group (0..127)
    const int b   = blockIdx.x & 7;    // batch (0..7)
    const int f0  = fg * 4;

    // twiddle table: tw[m] = e^{-2*pi*i*m/4096}, m < 256
    if (tid < TWN) {
        float s, co;
        sincospif((float)tid * (1.0f / 2048.0f), &s, &co);
        tw[PHYT(tid)] = make_float2(co, -s);
    }

    // Load + pack: z_c[n] = x[b, 2n, f0+c] + i*x[b, 2n+1, f0+c]
    const float *xb = x + ((size_t)b * 8192) * 512 + f0;
    for (int it = 0; it < 32; it++) {
        int idx = it * TPB + tid;
        int cc = idx & 3;
        int n  = idx >> 2;
        float xr = __ldg(xb + (size_t)(2 * n) * 512 + cc);
        float xi = __ldg(xb + (size_t)(2 * n + 1) * 512 + cc);
        sm[cc * CST + PHYS(n)] = make_float2(xr, xi);
    }
    __syncthreads();

    // ---- forward FFT (DIF radix-16 x3): output digit-reversed ----
    fwd_pass16<8>(sm, tw, tid);
    fwd_pass16<4>(sm, tw, tid);
    // final radix-16 blocks (no twiddles)
    #pragma unroll
    for (int it = 0; it < 2; it++) {
        int idx = it * TPB + tid;
        float2 *Bp = sm + (idx >> 8) * CST;
        int base = (idx & 255) * 16;
        int p0 = PHYS(base);
        float2 v[16];
        #pragma unroll
        for (int j = 0; j < 16; j++) v[j] = Bp[p0 + j];
        dft16(v);
        #pragma unroll
        for (int m = 0; m < 16; m++) Bp[p0 + m] = v[PERM16(m)];
    }
    __syncthreads();

    // ---- unpack -> filter -> repack (digit-reversed domain) ----
    for (int it = 0; it < 16; it++) {
        int idx = it * TPB + tid;
        int cc = idx >> 11;
        int q  = idx & 2047;
        float2 *Bp = sm + cc * CST;
        const float2 *Hb = H2 + (size_t)(f0 + cc) * 4097;
        if (q == 0) {
            float2 z0 = Bp[PHYS(0)];
            float X0 = z0.x + z0.y;
            float XN = z0.x - z0.y;
            float Y0 = X0 * __ldg(Hb + 0).x;
            float YN = XN * __ldg(Hb + 4096).x;
            Bp[PHYS(0)] = make_float2(0.5f * (Y0 + YN), 0.5f * (Y0 - YN));
        } else {
            // digit-shuffled enumeration of 1..2047: rev16(k) is thread-consecutive
            int k = ((q & 7) << 8) | (((q >> 3) & 15) << 4) | (q >> 7);
            filter_pair(Bp, Hb, k);
        }
    }
    if (tid < 4) {   // self-paired bin k = 2048
        filter_pair(sm + tid * CST, H2 + (size_t)(f0 + tid) * 4097, 2048);
    }
    __syncthreads();

    // ---- inverse FFT (DIT radix-16 x3): digit-reversed in, natural out ----
    #pragma unroll
    for (int it = 0; it < 2; it++) {
        int idx = it * TPB + tid;
        float2 *Bp = sm + (idx >> 8) * CST;
        int base = (idx & 255) * 16;
        int p0 = PHYS(base);
        float2 v[16];
        #pragma unroll
        for (int j = 0; j < 16; j++) {
            float2 u = Bp[p0 + j];
            v[j] = make_float2(u.x, -u.y);
        }
        dft16(v);
        #pragma unroll
        for (int m = 0; m < 16; m++) {
            float2 w = v[PERM16(m)];
            Bp[p0 + m] = make_float2(w.x, -w.y);
        }
    }
    __syncthreads();
    inv_pass16<4>(sm, tw, tid);
    inv_pass16<8>(sm, tw, tid);

    // ---- unpack to real output (scale 1/4096) ----
    float *yb = y + ((size_t)b * 8192) * 512 + f0;
    const float SC = 1.0f / 4096.0f;
    for (int it = 0; it < 32; it++) {
        int idx = it * TPB + tid;
        int cc = idx & 3;
        int n  = idx >> 2;
        float2 v = sm[cc * CST + PHYS(n)];
        yb[(size_t)(2 * n) * 512 + cc]     = v.x * SC;
        yb[(size_t)(2 * n + 1) * 512 + cc] = v.y * SC;
    }
}

extern "C" void kernel_launch(void* const* d_in, const int* in_sizes, int n_in,
                              void* d_out, int out_size) {
    (void)in_sizes; (void)n_in; (void)out_size;
    const float  *x  = (const float*)d_in[0];
    const float2 *H2 = (const float2*)d_in[1];
    float        *y  = (float*)d_out;

    const size_t smem_bytes = (size_t)(4 * CST + TWSZ) * sizeof(float2);  // ~141.7 KB
    cudaFuncSetAttribute(_ScaleFFTFilter_45380624449589_kernel,
                         cudaFuncAttributeMaxDynamicSharedMemorySize,
                         (int)smem_bytes);
    _ScaleFFTFilter_45380624449589_kernel<<<1024, TPB, smem_bytes>>>(x, H2, y);
}